// round 3
// baseline (speedup 1.0000x reference)
#include <cuda_runtime.h>
#include <math.h>
#include <stdint.h>

// Problem constants
constexpr int kB   = 4;
constexpr int kN   = 1024;
constexpr int kHID = 256;
constexpr int kNH  = 8;
constexpr int kDH  = 32;
constexpr int kBH  = 64;
constexpr int kROWS = kB * kN;          // 4096
constexpr int kT    = 8192;             // bias table resolution

constexpr int ATTN_SMEM = (2 * 64 * 256 + 64 * 8 * 32) * 4;  // 196608 bytes

// ---------------- scratch (no allocations allowed) ----------------
__device__ float g_xln[kROWS * kHID];        // layernormed x
__device__ float g_qkv[kROWS * 3 * kHID];    // qkv projection
__device__ float g_tab[kT * kNH];            // bias table (pre-scaled by log2e)
__device__ float g_ao [kROWS * kHID];        // attention output (pre-proj)

// ---------------- LayerNorm ----------------
__global__ void ln_kernel(const float* __restrict__ hin,
                          const float* __restrict__ gamma,
                          const float* __restrict__ beta)
{
    __shared__ float red[16];
    int row = blockIdx.x, t = threadIdx.x;
    float x = hin[(size_t)row * kHID + t];
    float s = x, s2 = x * x;
    #pragma unroll
    for (int off = 16; off; off >>= 1) {
        s  += __shfl_xor_sync(0xffffffffu, s,  off);
        s2 += __shfl_xor_sync(0xffffffffu, s2, off);
    }
    if ((t & 31) == 0) { red[t >> 5] = s; red[8 + (t >> 5)] = s2; }
    __syncthreads();
    float sum = 0.f, sum2 = 0.f;
    #pragma unroll
    for (int i = 0; i < 8; i++) { sum += red[i]; sum2 += red[8 + i]; }
    float mu  = sum * (1.0f / 256.0f);
    float var = sum2 * (1.0f / 256.0f) - mu * mu;
    float r   = rsqrtf(var + 1e-5f);
    g_xln[(size_t)row * kHID + t] = (x - mu) * r * gamma[t] + beta[t];
}

// ---------------- bias-table build: f(d) for d in [-1,1], 8192 pts ----------------
__global__ void __launch_bounds__(256) tab_kernel(
    const float* __restrict__ Wb1, const float* __restrict__ bb1,
    const float* __restrict__ Wb2, const float* __restrict__ bb2,
    const float* __restrict__ Wb3, const float* __restrict__ bb3)
{
    __shared__ float w1[64], c1[64], w2[64 * 64], c2[64], w3[64 * 8], c3[8];
    int t = threadIdx.x;
    if (t < 64) { w1[t] = Wb1[t]; c1[t] = bb1[t]; c2[t] = bb2[t]; }
    if (t < 8)  c3[t] = bb3[t];
    for (int i = t; i < 4096; i += 256) w2[i] = Wb2[i];
    for (int i = t; i < 512;  i += 256) w3[i] = Wb3[i];
    __syncthreads();

    int idx = blockIdx.x * 256 + t;
    float d = -1.0f + 2.0f * (float)idx / (float)(kT - 1);

    float h1[64];
    #pragma unroll
    for (int u = 0; u < 64; u++) {
        float a = fmaf(d, w1[u], c1[u]);
        h1[u] = a / (1.0f + expf(-a));           // silu
    }
    float acc[8];
    #pragma unroll
    for (int m = 0; m < 8; m++) acc[m] = c3[m];
    for (int u2 = 0; u2 < 64; u2++) {
        float a = c2[u2];
        #pragma unroll
        for (int u = 0; u < 64; u++) a = fmaf(h1[u], w2[u * 64 + u2], a);
        float sv = a / (1.0f + expf(-a));        // silu
        #pragma unroll
        for (int m = 0; m < 8; m++) acc[m] = fmaf(sv, w3[u2 * 8 + m], acc[m]);
    }
    const float LOG2E = 1.4426950408889634f;     // fold into table for exp2 softmax
    #pragma unroll
    for (int m = 0; m < 8; m++) g_tab[idx * 8 + m] = acc[m] * LOG2E;
}

// ---------------- generic fp32 GEMM: C[M,Nc] = A[M,K] @ W[K,Nc] + bias (+resid) ----------------
__global__ void __launch_bounds__(256) gemm64(
    const float* __restrict__ A, const float* __restrict__ W,
    const float* __restrict__ bias, const float* __restrict__ resid,
    float* __restrict__ C, int M, int Nc, int K)
{
    __shared__ float As[16][64];
    __shared__ float Bs[16][64];
    int t  = threadIdx.x;
    int n0 = blockIdx.x * 64, m0 = blockIdx.y * 64;
    int tm = t >> 4, tn = t & 15;
    int am = t >> 2, ak4 = (t & 3) * 4;
    int bk = t >> 4, bn4 = (t & 15) * 4;

    float acc[4][4] = {};
    for (int k0 = 0; k0 < K; k0 += 16) {
        float4 av = *(const float4*)(A + (size_t)(m0 + am) * K + k0 + ak4);
        float4 bv = *(const float4*)(W + (size_t)(k0 + bk) * Nc + n0 + bn4);
        As[ak4 + 0][am] = av.x; As[ak4 + 1][am] = av.y;
        As[ak4 + 2][am] = av.z; As[ak4 + 3][am] = av.w;
        *(float4*)&Bs[bk][bn4] = bv;
        __syncthreads();
        #pragma unroll
        for (int k = 0; k < 16; k++) {
            float4 a4 = *(const float4*)&As[k][tm * 4];
            float4 b4 = *(const float4*)&Bs[k][tn * 4];
            float ar[4] = {a4.x, a4.y, a4.z, a4.w};
            float br[4] = {b4.x, b4.y, b4.z, b4.w};
            #pragma unroll
            for (int i = 0; i < 4; i++)
                #pragma unroll
                for (int j = 0; j < 4; j++)
                    acc[i][j] = fmaf(ar[i], br[j], acc[i][j]);
        }
        __syncthreads();
    }
    #pragma unroll
    for (int i = 0; i < 4; i++) {
        int gm = m0 + tm * 4 + i;
        #pragma unroll
        for (int j = 0; j < 4; j++) {
            int gn = n0 + tn * 4 + j;
            float v = acc[i][j] + bias[gn];
            if (resid) v += resid[(size_t)gm * Nc + gn];
            C[(size_t)gm * Nc + gn] = v;
        }
    }
}

// ---------------- fused attention: block=(b, 32 queries), warp=head, lane=query ----------------
__global__ void __launch_bounds__(256, 1) attn_kernel(
    const float* __restrict__ coord, const int* __restrict__ mask)
{
    extern __shared__ float smf[];
    float* ks  = smf;                     // [64][256]
    float* vs  = smf + 64 * 256;          // [64][256]
    float* bsm = smf + 2 * 64 * 256;      // [64][8][32]  bias, later scores

    const int b    = blockIdx.y;
    const int q0   = blockIdx.x * 32;
    const int t    = threadIdx.x;
    const int hh   = t >> 5;              // head
    const int lane = t & 31;              // query within tile
    const int q    = q0 + lane;

    const float QSCALE = 1.4426950408889634f / sqrtf(32.0f);  // log2e / sqrt(DH)

    // Q row for (q, head) into registers, pre-scaled for exp2-domain softmax
    float qreg[32];
    {
        const float* qrow = g_qkv + ((size_t)(b * kN + q)) * 768 + hh * 32;
        #pragma unroll
        for (int d4 = 0; d4 < 8; d4++) {
            float4 v = *(const float4*)(qrow + d4 * 4);
            qreg[d4 * 4 + 0] = v.x * QSCALE;
            qreg[d4 * 4 + 1] = v.y * QSCALE;
            qreg[d4 * 4 + 2] = v.z * QSCALE;
            qreg[d4 * 4 + 3] = v.w * QSCALE;
        }
    }
    const float cq = coord[b * kN + q];

    float mrun = -1e30f, lrun = 0.f;
    float o[32];
    #pragma unroll
    for (int d = 0; d < 32; d++) o[d] = 0.f;

    for (int j0 = 0; j0 < kN; j0 += 64) {
        // ---- stage K/V tiles (coalesced float4) ----
        #pragma unroll
        for (int it = 0; it < 16; it++) {
            int idx = t + it * 256;
            int r = idx >> 6, c = (idx & 63) << 2;
            const float* src = g_qkv + ((size_t)(b * kN + j0 + r)) * 768;
            *(float4*)(ks + r * 256 + c) = *(const float4*)(src + 256 + c);
            *(float4*)(vs + r * 256 + c) = *(const float4*)(src + 512 + c);
        }
        // ---- stage bias tile: warp hh handles keys j = hh, hh+8, ... ----
        #pragma unroll
        for (int it = 0; it < 8; it++) {
            int j = hh + it * 8;
            float ck = coord[b * kN + j0 + j];     // broadcast load
            int   mk = mask [b * kN + j0 + j];
            float dd = ck - cq;
            float u  = (dd + 1.0f) * ((float)(kT - 1) * 0.5f);
            int i0 = (int)u;
            i0 = i0 < 0 ? 0 : (i0 > kT - 2 ? kT - 2 : i0);
            float fr = u - (float)i0;
            const float* tp = g_tab + i0 * 8;      // 8 heads contiguous = 1 sector
            float* dst = bsm + j * 256 + lane;     // bsm[j][m][lane]
            if (mk == 0) {
                #pragma unroll
                for (int m = 0; m < 8; m++) dst[m * 32] = -1e38f;
            } else {
                #pragma unroll
                for (int m = 0; m < 8; m++) {
                    float a = tp[m], bvl = tp[8 + m];
                    dst[m * 32] = fmaf(fr, bvl - a, a);
                }
            }
        }
        __syncthreads();

        // ---- pass 1: scores (in log2 domain) + tile max; s written back into bsm ----
        float tmax = mrun;
        const float* kbase = ks + hh * 32;
        float* srow = bsm + hh * 32 + lane;        // bsm[j][hh][lane]
        #pragma unroll 4
        for (int j = 0; j < 64; j++) {
            const float* kr = kbase + j * 256;
            float s0 = 0.f, s1 = 0.f, s2 = 0.f, s3 = 0.f;
            #pragma unroll
            for (int d4 = 0; d4 < 8; d4++) {
                float4 k4 = *(const float4*)(kr + d4 * 4);   // broadcast LDS.128
                s0 = fmaf(qreg[d4 * 4 + 0], k4.x, s0);
                s1 = fmaf(qreg[d4 * 4 + 1], k4.y, s1);
                s2 = fmaf(qreg[d4 * 4 + 2], k4.z, s2);
                s3 = fmaf(qreg[d4 * 4 + 3], k4.w, s3);
            }
            float s = (s0 + s1) + (s2 + s3) + srow[j * 256];
            srow[j * 256] = s;
            tmax = fmaxf(tmax, s);
        }
        // ---- online-softmax rescale (once per tile) ----
        float corr = exp2f(mrun - tmax);
        mrun = tmax;
        lrun *= corr;
        #pragma unroll
        for (int d = 0; d < 32; d++) o[d] *= corr;
        // ---- pass 2: p = exp2(s - m); accumulate l and o += p * v ----
        const float* vbase = vs + hh * 32;
        #pragma unroll 2
        for (int j = 0; j < 64; j++) {
            float p = exp2f(srow[j * 256] - mrun);
            lrun += p;
            const float* vr = vbase + j * 256;
            #pragma unroll
            for (int d4 = 0; d4 < 8; d4++) {
                float4 v4 = *(const float4*)(vr + d4 * 4);   // broadcast LDS.128
                o[d4 * 4 + 0] = fmaf(p, v4.x, o[d4 * 4 + 0]);
                o[d4 * 4 + 1] = fmaf(p, v4.y, o[d4 * 4 + 1]);
                o[d4 * 4 + 2] = fmaf(p, v4.z, o[d4 * 4 + 2]);
                o[d4 * 4 + 3] = fmaf(p, v4.w, o[d4 * 4 + 3]);
            }
        }
        __syncthreads();   // protect smem before next tile's staging
    }

    float inv = 1.0f / lrun;
    float* orow = g_ao + ((size_t)(b * kN + q)) * 256 + hh * 32;
    #pragma unroll
    for (int d4 = 0; d4 < 8; d4++) {
        float4 w;
        w.x = o[d4 * 4 + 0] * inv; w.y = o[d4 * 4 + 1] * inv;
        w.z = o[d4 * 4 + 2] * inv; w.w = o[d4 * 4 + 3] * inv;
        *(float4*)(orow + d4 * 4) = w;
    }
}

// ---------------- launch ----------------
extern "C" void kernel_launch(void* const* d_in, const int* in_sizes, int n_in,
                              void* d_out, int out_size)
{
    const float* hin   = (const float*)d_in[0];
    const float* coord = (const float*)d_in[1];
    const int*   mask  = (const int*)  d_in[2];
    const float* Wqkv  = (const float*)d_in[3];
    const float* bqkv  = (const float*)d_in[4];
    const float* Wproj = (const float*)d_in[5];
    const float* bproj = (const float*)d_in[6];
    const float* gamma = (const float*)d_in[7];
    const float* beta  = (const float*)d_in[8];
    const float* Wb1   = (const float*)d_in[9];
    const float* bb1   = (const float*)d_in[10];
    const float* Wb2   = (const float*)d_in[11];
    const float* bb2   = (const float*)d_in[12];
    const float* Wb3   = (const float*)d_in[13];
    const float* bb3   = (const float*)d_in[14];
    float* out = (float*)d_out;

    void *p_xln, *p_qkv, *p_ao;
    cudaGetSymbolAddress(&p_xln, g_xln);
    cudaGetSymbolAddress(&p_qkv, g_qkv);
    cudaGetSymbolAddress(&p_ao,  g_ao);

    cudaFuncSetAttribute(attn_kernel, cudaFuncAttributeMaxDynamicSharedMemorySize, ATTN_SMEM);

    // independent: bias table
    tab_kernel<<<kT / 256, 256>>>(Wb1, bb1, Wb2, bb2, Wb3, bb3);
    // layernorm
    ln_kernel<<<kROWS, 256>>>(hin, gamma, beta);
    // qkv = xln @ Wqkv + bqkv
    gemm64<<<dim3(768 / 64, kROWS / 64), 256>>>((const float*)p_xln, Wqkv, bqkv, nullptr,
                                                (float*)p_qkv, kROWS, 768, 256);
    // fused bias-lookup flash attention
    attn_kernel<<<dim3(kN / 32, kB), 256, ATTN_SMEM>>>(coord, mask);
    // out = h + ao @ Wproj + bproj
    gemm64<<<dim3(256 / 64, kROWS / 64), 256>>>((const float*)p_ao, Wproj, bproj, hin,
                                                out, kROWS, 256, 256);
}

// round 4
// speedup vs baseline: 1.1317x; 1.1317x over previous
#include <cuda_runtime.h>
#include <math.h>
#include <stdint.h>

// Problem constants
constexpr int kB   = 4;
constexpr int kN   = 1024;
constexpr int kHID = 256;
constexpr int kNH  = 8;
constexpr int kDH  = 32;
constexpr int kBH  = 64;
constexpr int kROWS = kB * kN;          // 4096
constexpr int kT    = 8192;             // bias table resolution
constexpr int kSPLIT = 2;               // key-dim split factor
constexpr int kJT  = 32;                // key tile per iteration

// smem: K[32][256] + V[32][256] + bias/scores[32][8][32]  = 96 KB
constexpr int ATTN_SMEM = (2 * kJT * 256 + kJT * 8 * 32) * 4;

// ---------------- scratch (no allocations allowed) ----------------
__device__ float g_xln[kROWS * kHID];              // layernormed x
__device__ float g_qkv[kROWS * 3 * kHID];          // qkv projection
__device__ float g_tab[kT * kNH];                  // bias table (pre-scaled by log2e)
__device__ float g_ao [kROWS * kHID];              // attention output (pre-proj)
__device__ float g_po [kSPLIT * kROWS * kHID];     // partial (unnormalized) outputs
__device__ float g_pm [kSPLIT * kROWS * kNH];      // partial running max (log2 domain)
__device__ float g_pl [kSPLIT * kROWS * kNH];      // partial running denom

// ---------------- LayerNorm ----------------
__global__ void ln_kernel(const float* __restrict__ hin,
                          const float* __restrict__ gamma,
                          const float* __restrict__ beta)
{
    __shared__ float red[16];
    int row = blockIdx.x, t = threadIdx.x;
    float x = hin[(size_t)row * kHID + t];
    float s = x, s2 = x * x;
    #pragma unroll
    for (int off = 16; off; off >>= 1) {
        s  += __shfl_xor_sync(0xffffffffu, s,  off);
        s2 += __shfl_xor_sync(0xffffffffu, s2, off);
    }
    if ((t & 31) == 0) { red[t >> 5] = s; red[8 + (t >> 5)] = s2; }
    __syncthreads();
    float sum = 0.f, sum2 = 0.f;
    #pragma unroll
    for (int i = 0; i < 8; i++) { sum += red[i]; sum2 += red[8 + i]; }
    float mu  = sum * (1.0f / 256.0f);
    float var = sum2 * (1.0f / 256.0f) - mu * mu;
    float r   = rsqrtf(var + 1e-5f);
    g_xln[(size_t)row * kHID + t] = (x - mu) * r * gamma[t] + beta[t];
}

// ---------------- bias-table build: f(d) for d in [-1,1], 8192 pts ----------------
__global__ void __launch_bounds__(256) tab_kernel(
    const float* __restrict__ Wb1, const float* __restrict__ bb1,
    const float* __restrict__ Wb2, const float* __restrict__ bb2,
    const float* __restrict__ Wb3, const float* __restrict__ bb3)
{
    __shared__ float w1[64], c1[64], w2[64 * 64], c2[64], w3[64 * 8], c3[8];
    int t = threadIdx.x;
    if (t < 64) { w1[t] = Wb1[t]; c1[t] = bb1[t]; c2[t] = bb2[t]; }
    if (t < 8)  c3[t] = bb3[t];
    for (int i = t; i < 4096; i += 256) w2[i] = Wb2[i];
    for (int i = t; i < 512;  i += 256) w3[i] = Wb3[i];
    __syncthreads();

    int idx = blockIdx.x * 256 + t;
    float d = -1.0f + 2.0f * (float)idx / (float)(kT - 1);

    float h1[64];
    #pragma unroll
    for (int u = 0; u < 64; u++) {
        float a = fmaf(d, w1[u], c1[u]);
        h1[u] = a / (1.0f + expf(-a));           // silu
    }
    float acc[8];
    #pragma unroll
    for (int m = 0; m < 8; m++) acc[m] = c3[m];
    for (int u2 = 0; u2 < 64; u2++) {
        float a = c2[u2];
        #pragma unroll
        for (int u = 0; u < 64; u++) a = fmaf(h1[u], w2[u * 64 + u2], a);
        float sv = a / (1.0f + expf(-a));        // silu
        #pragma unroll
        for (int m = 0; m < 8; m++) acc[m] = fmaf(sv, w3[u2 * 8 + m], acc[m]);
    }
    const float LOG2E = 1.4426950408889634f;     // fold into table for exp2 softmax
    #pragma unroll
    for (int m = 0; m < 8; m++) g_tab[idx * 8 + m] = acc[m] * LOG2E;
}

// ---------------- generic fp32 GEMM: C[M,Nc] = A[M,K] @ W[K,Nc] + bias (+resid) ----------------
__global__ void __launch_bounds__(256) gemm64(
    const float* __restrict__ A, const float* __restrict__ W,
    const float* __restrict__ bias, const float* __restrict__ resid,
    float* __restrict__ C, int M, int Nc, int K)
{
    __shared__ float As[16][64];
    __shared__ float Bs[16][64];
    int t  = threadIdx.x;
    int n0 = blockIdx.x * 64, m0 = blockIdx.y * 64;
    int tm = t >> 4, tn = t & 15;
    int am = t >> 2, ak4 = (t & 3) * 4;
    int bk = t >> 4, bn4 = (t & 15) * 4;

    float acc[4][4] = {};
    for (int k0 = 0; k0 < K; k0 += 16) {
        float4 av = *(const float4*)(A + (size_t)(m0 + am) * K + k0 + ak4);
        float4 bv = *(const float4*)(W + (size_t)(k0 + bk) * Nc + n0 + bn4);
        As[ak4 + 0][am] = av.x; As[ak4 + 1][am] = av.y;
        As[ak4 + 2][am] = av.z; As[ak4 + 3][am] = av.w;
        *(float4*)&Bs[bk][bn4] = bv;
        __syncthreads();
        #pragma unroll
        for (int k = 0; k < 16; k++) {
            float4 a4 = *(const float4*)&As[k][tm * 4];
            float4 b4 = *(const float4*)&Bs[k][tn * 4];
            float ar[4] = {a4.x, a4.y, a4.z, a4.w};
            float br[4] = {b4.x, b4.y, b4.z, b4.w};
            #pragma unroll
            for (int i = 0; i < 4; i++)
                #pragma unroll
                for (int j = 0; j < 4; j++)
                    acc[i][j] = fmaf(ar[i], br[j], acc[i][j]);
        }
        __syncthreads();
    }
    #pragma unroll
    for (int i = 0; i < 4; i++) {
        int gm = m0 + tm * 4 + i;
        #pragma unroll
        for (int j = 0; j < 4; j++) {
            int gn = n0 + tn * 4 + j;
            float v = acc[i][j] + bias[gn];
            if (resid) v += resid[(size_t)gm * Nc + gn];
            C[(size_t)gm * Nc + gn] = v;
        }
    }
}

// ---------------- fused attention (split-KV): block=(b, 32q, key-half) ----------------
// warp = head, lane = query. Each CTA covers 512 keys; partials merged later.
__global__ void __launch_bounds__(256, 2) attn_kernel(
    const float* __restrict__ coord, const int* __restrict__ mask)
{
    extern __shared__ float smf[];
    float* ks  = smf;                          // [32][256]
    float* vs  = smf + kJT * 256;              // [32][256]
    float* bsm = smf + 2 * kJT * 256;          // [32][8][32]  bias, later scores

    const int b    = blockIdx.y;
    const int q0   = blockIdx.x * 32;
    const int kh   = blockIdx.z;               // key-half
    const int t    = threadIdx.x;
    const int hh   = t >> 5;                   // head
    const int lane = t & 31;                   // query within tile
    const int q    = q0 + lane;

    const float QSCALE = 1.4426950408889634f / sqrtf(32.0f);  // log2e / sqrt(DH)

    // Q row for (q, head) into registers, pre-scaled for exp2-domain softmax
    float qreg[32];
    {
        const float* qrow = g_qkv + ((size_t)(b * kN + q)) * 768 + hh * 32;
        #pragma unroll
        for (int d4 = 0; d4 < 8; d4++) {
            float4 v = *(const float4*)(qrow + d4 * 4);
            qreg[d4 * 4 + 0] = v.x * QSCALE;
            qreg[d4 * 4 + 1] = v.y * QSCALE;
            qreg[d4 * 4 + 2] = v.z * QSCALE;
            qreg[d4 * 4 + 3] = v.w * QSCALE;
        }
    }
    const float cq = coord[b * kN + q];

    float mrun = -1e30f, lrun = 0.f;
    float o[32];
    #pragma unroll
    for (int d = 0; d < 32; d++) o[d] = 0.f;

    const int jbeg = kh * (kN / kSPLIT);
    const int jend = jbeg + (kN / kSPLIT);

    for (int j0 = jbeg; j0 < jend; j0 += kJT) {
        // ---- stage K/V tiles (coalesced float4): 32 rows x 64 float4 each ----
        #pragma unroll
        for (int it = 0; it < 8; it++) {
            int idx = t + it * 256;
            int r = idx >> 6, c = (idx & 63) << 2;
            const float* src = g_qkv + ((size_t)(b * kN + j0 + r)) * 768;
            *(float4*)(ks + r * 256 + c) = *(const float4*)(src + 256 + c);
            *(float4*)(vs + r * 256 + c) = *(const float4*)(src + 512 + c);
        }
        // ---- stage bias tile: warp hh handles keys j = hh, hh+8, hh+16, hh+24 ----
        #pragma unroll
        for (int it = 0; it < 4; it++) {
            int j = hh + it * 8;
            float ck = coord[b * kN + j0 + j];     // broadcast load
            int   mk = mask [b * kN + j0 + j];
            float dd = ck - cq;
            float u  = (dd + 1.0f) * ((float)(kT - 1) * 0.5f);
            int i0 = (int)u;
            i0 = i0 < 0 ? 0 : (i0 > kT - 2 ? kT - 2 : i0);
            float fr = u - (float)i0;
            const float* tp = g_tab + i0 * 8;      // 8 heads contiguous
            float* dst = bsm + j * 256 + lane;     // bsm[j][m][lane]
            if (mk == 0) {
                #pragma unroll
                for (int m = 0; m < 8; m++) dst[m * 32] = -1e38f;
            } else {
                #pragma unroll
                for (int m = 0; m < 8; m++) {
                    float a = tp[m], bvl = tp[8 + m];
                    dst[m * 32] = fmaf(fr, bvl - a, a);
                }
            }
        }
        __syncthreads();

        // ---- pass 1: scores (log2 domain) + tile max; s written back into bsm ----
        float tmax = mrun;
        const float* kbase = ks + hh * 32;
        float* srow = bsm + hh * 32 + lane;        // bsm[j][hh][lane]
        #pragma unroll 2
        for (int j = 0; j < kJT; j++) {
            const float* kr = kbase + j * 256;
            float s0 = 0.f, s1 = 0.f, s2 = 0.f, s3 = 0.f;
            #pragma unroll
            for (int d4 = 0; d4 < 8; d4++) {
                float4 k4 = *(const float4*)(kr + d4 * 4);   // broadcast LDS.128
                s0 = fmaf(qreg[d4 * 4 + 0], k4.x, s0);
                s1 = fmaf(qreg[d4 * 4 + 1], k4.y, s1);
                s2 = fmaf(qreg[d4 * 4 + 2], k4.z, s2);
                s3 = fmaf(qreg[d4 * 4 + 3], k4.w, s3);
            }
            float s = (s0 + s1) + (s2 + s3) + srow[j * 256];
            srow[j * 256] = s;
            tmax = fmaxf(tmax, s);
        }
        // ---- online-softmax rescale (once per tile) ----
        float corr = exp2f(mrun - tmax);
        mrun = tmax;
        lrun *= corr;
        #pragma unroll
        for (int d = 0; d < 32; d++) o[d] *= corr;
        // ---- pass 2: p = exp2(s - m); accumulate l and o += p * v ----
        const float* vbase = vs + hh * 32;
        #pragma unroll 2
        for (int j = 0; j < kJT; j++) {
            float p = exp2f(srow[j * 256] - mrun);
            lrun += p;
            const float* vr = vbase + j * 256;
            #pragma unroll
            for (int d4 = 0; d4 < 8; d4++) {
                float4 v4 = *(const float4*)(vr + d4 * 4);   // broadcast LDS.128
                o[d4 * 4 + 0] = fmaf(p, v4.x, o[d4 * 4 + 0]);
                o[d4 * 4 + 1] = fmaf(p, v4.y, o[d4 * 4 + 1]);
                o[d4 * 4 + 2] = fmaf(p, v4.z, o[d4 * 4 + 2]);
                o[d4 * 4 + 3] = fmaf(p, v4.w, o[d4 * 4 + 3]);
            }
        }
        __syncthreads();   // protect smem before next tile's staging
    }

    // ---- write unnormalized partials + (m, l) ----
    float* orow = g_po + (size_t)kh * (kROWS * kHID)
                + ((size_t)(b * kN + q)) * 256 + hh * 32;
    #pragma unroll
    for (int d4 = 0; d4 < 8; d4++) {
        float4 w;
        w.x = o[d4 * 4 + 0]; w.y = o[d4 * 4 + 1];
        w.z = o[d4 * 4 + 2]; w.w = o[d4 * 4 + 3];
        *(float4*)(orow + d4 * 4) = w;
    }
    int mlidx = kh * (kROWS * kNH) + (b * kN + q) * 8 + hh;
    g_pm[mlidx] = mrun;
    g_pl[mlidx] = lrun;
}

// ---------------- combine the kSPLIT partials into g_ao ----------------
__global__ void __launch_bounds__(256) combine_kernel()
{
    int idx  = blockIdx.x * 256 + threadIdx.x;   // 4096*8*8 = 262144 threads
    int rowh = idx >> 3;                         // (row, head)
    int d4   = idx & 7;
    int row  = rowh >> 3;
    int h    = rowh & 7;

    float m0 = g_pm[rowh];
    float m1 = g_pm[kROWS * kNH + rowh];
    float l0 = g_pl[rowh];
    float l1 = g_pl[kROWS * kNH + rowh];
    float M  = fmaxf(m0, m1);
    float w0 = exp2f(m0 - M), w1 = exp2f(m1 - M);
    float inv = 1.0f / (l0 * w0 + l1 * w1);

    size_t off = (size_t)row * 256 + h * 32 + d4 * 4;
    float4 o0 = *(const float4*)(g_po + off);
    float4 o1 = *(const float4*)(g_po + (size_t)(kROWS * kHID) + off);
    float4 r;
    r.x = (o0.x * w0 + o1.x * w1) * inv;
    r.y = (o0.y * w0 + o1.y * w1) * inv;
    r.z = (o0.z * w0 + o1.z * w1) * inv;
    r.w = (o0.w * w0 + o1.w * w1) * inv;
    *(float4*)(g_ao + off) = r;
}

// ---------------- launch ----------------
extern "C" void kernel_launch(void* const* d_in, const int* in_sizes, int n_in,
                              void* d_out, int out_size)
{
    const float* hin   = (const float*)d_in[0];
    const float* coord = (const float*)d_in[1];
    const int*   mask  = (const int*)  d_in[2];
    const float* Wqkv  = (const float*)d_in[3];
    const float* bqkv  = (const float*)d_in[4];
    const float* Wproj = (const float*)d_in[5];
    const float* bproj = (const float*)d_in[6];
    const float* gamma = (const float*)d_in[7];
    const float* beta  = (const float*)d_in[8];
    const float* Wb1   = (const float*)d_in[9];
    const float* bb1   = (const float*)d_in[10];
    const float* Wb2   = (const float*)d_in[11];
    const float* bb2   = (const float*)d_in[12];
    const float* Wb3   = (const float*)d_in[13];
    const float* bb3   = (const float*)d_in[14];
    float* out = (float*)d_out;

    void *p_xln, *p_qkv, *p_ao;
    cudaGetSymbolAddress(&p_xln, g_xln);
    cudaGetSymbolAddress(&p_qkv, g_qkv);
    cudaGetSymbolAddress(&p_ao,  g_ao);

    cudaFuncSetAttribute(attn_kernel, cudaFuncAttributeMaxDynamicSharedMemorySize, ATTN_SMEM);

    // independent: bias table
    tab_kernel<<<kT / 256, 256>>>(Wb1, bb1, Wb2, bb2, Wb3, bb3);
    // layernorm
    ln_kernel<<<kROWS, 256>>>(hin, gamma, beta);
    // qkv = xln @ Wqkv + bqkv
    gemm64<<<dim3(768 / 64, kROWS / 64), 256>>>((const float*)p_xln, Wqkv, bqkv, nullptr,
                                                (float*)p_qkv, kROWS, 768, 256);
    // fused bias-lookup flash attention, 2-way split over keys
    attn_kernel<<<dim3(kN / 32, kB, kSPLIT), 256, ATTN_SMEM>>>(coord, mask);
    // merge partials
    combine_kernel<<<(kROWS * kNH * 8) / 256, 256>>>();
    // out = h + ao @ Wproj + bproj
    gemm64<<<dim3(256 / 64, kROWS / 64), 256>>>((const float*)p_ao, Wproj, bproj, hin,
                                                out, kROWS, 256, 256);
}